// round 9
// baseline (speedup 1.0000x reference)
#include <cuda_runtime.h>
#include <cuda_bf16.h>
#include <cstdint>

#define N_NODES 50000
#define N_EDGES 800000
#define IN_DIM  256
#define HIDDEN  128
#define OUT_DIM 64
#define NEG_SLOPE 0.1f

// ============================ PTX helpers (sm_80+ baseline) ==================
__device__ __forceinline__ uint32_t smem_u32(const void* p) {
    uint32_t a;
    asm("{ .reg .u64 t; cvta.to.shared.u64 t, %1; cvt.u32.u64 %0, t; }"
        : "=r"(a) : "l"(p));
    return a;
}
#define LDMX4(R, addr) \
    asm volatile("ldmatrix.sync.aligned.m8n8.x4.shared.b16 {%0,%1,%2,%3}, [%4];" \
        : "=r"((R)[0]), "=r"((R)[1]), "=r"((R)[2]), "=r"((R)[3]) : "r"(addr))
#define MMA16816(d, a, b) \
    asm volatile("mma.sync.aligned.m16n8k16.row.col.f32.bf16.bf16.f32 " \
        "{%0,%1,%2,%3},{%4,%5,%6,%7},{%8,%9},{%0,%1,%2,%3};" \
        : "+f"((d)[0]), "+f"((d)[1]), "+f"((d)[2]), "+f"((d)[3]) \
        : "r"((a)[0]), "r"((a)[1]), "r"((a)[2]), "r"((a)[3]), \
          "r"((b)[0]), "r"((b)[1]))

__device__ __forceinline__ uint32_t pack_bf2(__nv_bfloat16 a, __nv_bfloat16 b) {
    __nv_bfloat162 p; p.x = a; p.y = b;
    return *(uint32_t*)&p;
}

// ---------------- scratch (static __device__, no allocation) ----------------
__device__ __align__(256) float g_buf0[N_NODES * HIDDEN];
__device__ __align__(256) float g_buf1[N_NODES * HIDDEN];
__device__ float g_dinv[N_NODES];
__device__ int   g_cnt[N_NODES];
__device__ int   g_wp[N_NODES];
__device__ int   g_rowptr[N_NODES + 1];
__device__ int   g_col[N_EDGES];
__device__ int   g_is64;
// pre-transposed + bf16-split weights: Wt[n][k] hi/lo
__device__ __align__(16) __nv_bfloat16 g_wthi_enc[HIDDEN * IN_DIM];
__device__ __align__(16) __nv_bfloat16 g_wtlo_enc[HIDDEN * IN_DIM];
__device__ __align__(16) __nv_bfloat16 g_wthi_conv[2 * HIDDEN * HIDDEN];
__device__ __align__(16) __nv_bfloat16 g_wtlo_conv[2 * HIDDEN * HIDDEN];
__device__ __align__(16) __nv_bfloat16 g_wthi_dec[OUT_DIM * HIDDEN];
__device__ __align__(16) __nv_bfloat16 g_wtlo_dec[OUT_DIM * HIDDEN];

__device__ __forceinline__ const float* resolve_c(const float* p, int sel) {
    if (sel == 0) return g_buf0;
    if (sel == 1) return g_buf1;
    return p;
}
__device__ __forceinline__ float* resolve_m(float* p, int sel) {
    if (sel == 0) return g_buf0;
    if (sel == 1) return g_buf1;
    return p;
}

__device__ __forceinline__ int edge_at(const void* ei, int which, int i) {
    if (g_is64) return (int)((const long long*)ei)[(size_t)which * N_EDGES + i];
    return ((const int*)ei)[which * N_EDGES + i];
}

// ---------------- merged preprocessing ----------------
__global__ void k_pre0(const void* __restrict__ ei) {
    int i = blockIdx.x * blockDim.x + threadIdx.x;
    if (i < N_NODES) { g_cnt[i] = 0; g_wp[i] = 0; }
    if (blockIdx.x == 0) {
        __shared__ int bad64;
        if (threadIdx.x == 0) bad64 = 0;
        __syncthreads();
        const long long* p64 = (const long long*)ei;
        int local = 0;
        for (int t = threadIdx.x; t < 2048; t += blockDim.x) {
            long long v = p64[(long long)t * 390];
            if (v < 0 || v >= N_NODES) local++;
        }
        if (local) atomicAdd(&bad64, local);
        __syncthreads();
        if (threadIdx.x == 0) g_is64 = (bad64 == 0) ? 1 : 0;
    }
}

// degree count (2 edges/thread, first blocks) + weight split (tail blocks)
#define COUNT_BLKS ((N_EDGES / 2 + 255) / 256)      /* 1563 */
#define PREPW_TOT  (HIDDEN * IN_DIM + 2 * HIDDEN * HIDDEN + OUT_DIM * HIDDEN)
#define PREPW_BLKS ((PREPW_TOT + 255) / 256)        /* 288 */
__global__ void k_count_prep(const void* __restrict__ ei,
                             const float* __restrict__ enc_W,
                             const float* __restrict__ conv_W,
                             const float* __restrict__ dec_W) {
    if (blockIdx.x < COUNT_BLKS) {
        int i = (blockIdx.x * 256 + threadIdx.x) * 2;
        if (i < N_EDGES) {
            int d0 = edge_at(ei, 1, i);
            int d1 = (i + 1 < N_EDGES) ? edge_at(ei, 1, i + 1) : -1;
            if ((unsigned)d0 < N_NODES) atomicAdd(&g_cnt[d0], 1);
            if ((unsigned)d1 < N_NODES) atomicAdd(&g_cnt[d1], 1);
        }
    } else {
        int idx = (blockIdx.x - COUNT_BLKS) * 256 + threadIdx.x;
        const int E0 = HIDDEN * IN_DIM;
        const int C0 = E0 + 2 * HIDDEN * HIDDEN;
        if (idx >= PREPW_TOT) return;
        const float* W; __nv_bfloat16 *hi, *lo; int K, N, li;
        if (idx < E0) { W = enc_W; hi = g_wthi_enc; lo = g_wtlo_enc; K = IN_DIM; N = HIDDEN; li = idx; }
        else if (idx < C0) {
            int j = idx - E0; int which = j / (HIDDEN * HIDDEN); li = j % (HIDDEN * HIDDEN);
            W = conv_W + (size_t)which * HIDDEN * HIDDEN;
            hi = g_wthi_conv + (size_t)which * HIDDEN * HIDDEN;
            lo = g_wtlo_conv + (size_t)which * HIDDEN * HIDDEN;
            K = HIDDEN; N = HIDDEN;
        } else { li = idx - C0; W = dec_W; hi = g_wthi_dec; lo = g_wtlo_dec; K = HIDDEN; N = OUT_DIM; }
        int k = li / N, n = li % N;
        float v = W[(size_t)k * N + n];
        __nv_bfloat16 h = __float2bfloat16(v);
        float r = v - __bfloat162float(h);
        hi[(size_t)n * K + k] = h;
        lo[(size_t)n * K + k] = __float2bfloat16(r);
    }
}

// single-block scan + dinv
__global__ void k_scan_dinv() {
    __shared__ int sh[1024];
    const int tid = threadIdx.x;
    const int CH = (N_NODES + 1023) / 1024;
    int start = tid * CH;
    int end   = start + CH; if (end > N_NODES) end = N_NODES;
    int s = 0;
    for (int i = start; i < end; i++) {
        int c = g_cnt[i];
        s += c;
        g_dinv[i] = rsqrtf((float)(c + 1));
    }
    sh[tid] = s;
    __syncthreads();
    for (int d = 1; d < 1024; d <<= 1) {
        int t = (tid >= d) ? sh[tid - d] : 0;
        __syncthreads();
        sh[tid] += t;
        __syncthreads();
    }
    int off = sh[tid] - s;
    for (int i = start; i < end; i++) { g_rowptr[i] = off; off += g_cnt[i]; }
    if (start < N_NODES && end == N_NODES) g_rowptr[N_NODES] = off;
}

// CSR fill, 2 edges per thread
__global__ void k_fill(const void* __restrict__ ei) {
    int i = (blockIdx.x * blockDim.x + threadIdx.x) * 2;
    if (i >= N_EDGES) return;
    int s0 = edge_at(ei, 0, i);
    int d0 = edge_at(ei, 1, i);
    int s1 = -1, d1 = -1;
    if (i + 1 < N_EDGES) { s1 = edge_at(ei, 0, i + 1); d1 = edge_at(ei, 1, i + 1); }
    if ((unsigned)d0 < N_NODES && (unsigned)s0 < N_NODES) {
        int pos = g_rowptr[d0] + atomicAdd(&g_wp[d0], 1);
        g_col[pos] = s0;
    }
    if ((unsigned)d1 < N_NODES && (unsigned)s1 < N_NODES) {
        int pos = g_rowptr[d1] + atomicAdd(&g_wp[d1], 1);
        g_col[pos] = s1;
    }
}

// ---------------- aggregation: one warp per node ----------------
// Input rows pre-scaled: h'[n] = dinv[n]*h[n] (done in GEMM epilogue).
// out[n] = dinv[n] * ( sum_{s in nbr(n)} h'[s] + h'[n] )
__global__ void k_agg(int in_sel, int out_sel) {
    const float* __restrict__ h = resolve_c(nullptr, in_sel);
    float* __restrict__ out = resolve_m(nullptr, out_sel);
    int warp = (blockIdx.x * blockDim.x + threadIdx.x) >> 5;
    int lane = threadIdx.x & 31;
    if (warp >= N_NODES) return;
    const int node = warp;
    const float dn = g_dinv[node];

    float4 a0 = *(const float4*)&h[(size_t)node * HIDDEN + lane * 4]; // self h'
    float4 a1 = make_float4(0.f, 0.f, 0.f, 0.f);
    float4 a2 = make_float4(0.f, 0.f, 0.f, 0.f);
    float4 a3 = make_float4(0.f, 0.f, 0.f, 0.f);

    const int beg = g_rowptr[node];
    const int end = g_rowptr[node + 1];
    int j = beg;
    for (; j + 4 <= end; j += 4) {
        int s0 = g_col[j + 0];
        int s1 = g_col[j + 1];
        int s2 = g_col[j + 2];
        int s3 = g_col[j + 3];
        float4 v0 = *(const float4*)&h[(size_t)s0 * HIDDEN + lane * 4];
        float4 v1 = *(const float4*)&h[(size_t)s1 * HIDDEN + lane * 4];
        float4 v2 = *(const float4*)&h[(size_t)s2 * HIDDEN + lane * 4];
        float4 v3 = *(const float4*)&h[(size_t)s3 * HIDDEN + lane * 4];
        a0.x += v0.x; a0.y += v0.y; a0.z += v0.z; a0.w += v0.w;
        a1.x += v1.x; a1.y += v1.y; a1.z += v1.z; a1.w += v1.w;
        a2.x += v2.x; a2.y += v2.y; a2.z += v2.z; a2.w += v2.w;
        a3.x += v3.x; a3.y += v3.y; a3.z += v3.z; a3.w += v3.w;
    }
    for (; j < end; j++) {
        int s = g_col[j];
        float4 v = *(const float4*)&h[(size_t)s * HIDDEN + lane * 4];
        a0.x += v.x; a0.y += v.y; a0.z += v.z; a0.w += v.w;
    }
    float4 r;
    r.x = dn * ((a0.x + a1.x) + (a2.x + a3.x));
    r.y = dn * ((a0.y + a1.y) + (a2.y + a3.y));
    r.z = dn * ((a0.z + a1.z) + (a2.z + a3.z));
    r.w = dn * ((a0.w + a1.w) + (a2.w + a3.w));
    *(float4*)&out[(size_t)node * HIDDEN + lane * 4] = r;
}

// ============ bf16x3 GEMM via mma.sync.m16n8k16 (sm_80+ baseline) ============
// C[M,N] = act(A[M,KTOT] @ W + b) [optionally * dinv[row]].
// CTA: 256 thr = 8 warps (4m x 2n).  BM=128, BN=N, BK=32.
template <int KTOT, int N, int WSEL, bool ACT, bool SCALE>
__global__ void __launch_bounds__(256, 1)
gemm_mma(const float* __restrict__ A_ext, int a_sel,
         const float* __restrict__ bias,
         float* __restrict__ C_ext, int c_sel, int M) {
    constexpr int NTPW = N / 16;
    const float* __restrict__ A = resolve_c(A_ext, a_sel);
    float* __restrict__ C = resolve_m(C_ext, c_sel);
    const __nv_bfloat16* __restrict__ WtHi;
    const __nv_bfloat16* __restrict__ WtLo;
    if (WSEL == 0)      { WtHi = g_wthi_enc;  WtLo = g_wtlo_enc; }
    else if (WSEL == 1) { WtHi = g_wthi_conv; WtLo = g_wtlo_conv; }
    else if (WSEL == 2) { WtHi = g_wthi_conv + HIDDEN * HIDDEN;
                          WtLo = g_wtlo_conv + HIDDEN * HIDDEN; }
    else                { WtHi = g_wthi_dec;  WtLo = g_wtlo_dec; }

    __shared__ __align__(16) __nv_bfloat16 sAhi[128][40];
    __shared__ __align__(16) __nv_bfloat16 sAlo[128][40];
    __shared__ __align__(16) __nv_bfloat16 sBhi[N][40];
    __shared__ __align__(16) __nv_bfloat16 sBlo[N][40];

    const int tid  = threadIdx.x;
    const int lane = tid & 31;
    const int wid  = tid >> 5;
    const int wm   = wid & 3;
    const int wn   = wid >> 2;
    const int block_row = blockIdx.x * 128;

    float acc[2][NTPW][4];
#pragma unroll
    for (int mt = 0; mt < 2; mt++)
#pragma unroll
        for (int nt = 0; nt < NTPW; nt++)
#pragma unroll
            for (int j = 0; j < 4; j++) acc[mt][nt][j] = 0.0f;

    for (int k0 = 0; k0 < KTOT; k0 += 32) {
        {
            const int row  = tid >> 1;
            const int half = tid & 1;
            const int gr   = block_row + row;
            const float* src = A + (size_t)gr * KTOT + k0 + half * 16;
            const bool ok = gr < M;
#pragma unroll
            for (int j = 0; j < 4; j++) {
                float4 v = ok ? *(const float4*)(src + j * 4)
                              : make_float4(0.f, 0.f, 0.f, 0.f);
                __nv_bfloat16 hx = __float2bfloat16(v.x);
                __nv_bfloat16 hy = __float2bfloat16(v.y);
                __nv_bfloat16 hz = __float2bfloat16(v.z);
                __nv_bfloat16 hw = __float2bfloat16(v.w);
                __nv_bfloat16 lx = __float2bfloat16(v.x - __bfloat162float(hx));
                __nv_bfloat16 ly = __float2bfloat16(v.y - __bfloat162float(hy));
                __nv_bfloat16 lz = __float2bfloat16(v.z - __bfloat162float(hz));
                __nv_bfloat16 lw = __float2bfloat16(v.w - __bfloat162float(hw));
                int col = half * 16 + j * 4;
                *(uint2*)&sAhi[row][col] = make_uint2(pack_bf2(hx, hy), pack_bf2(hz, hw));
                *(uint2*)&sAlo[row][col] = make_uint2(pack_bf2(lx, ly), pack_bf2(lz, lw));
            }
        }
#pragma unroll
        for (int i = tid; i < N * 4; i += 256) {
            int row = i >> 2, q = i & 3;
            *(uint4*)&sBhi[row][q * 8] =
                *(const uint4*)(WtHi + (size_t)row * KTOT + k0 + q * 8);
            *(uint4*)&sBlo[row][q * 8] =
                *(const uint4*)(WtLo + (size_t)row * KTOT + k0 + q * 8);
        }
        __syncthreads();

#pragma unroll
        for (int ks = 0; ks < 2; ks++) {
            const int kb = ks * 16;
            uint32_t ahi[2][4], alo[2][4];
#pragma unroll
            for (int mt = 0; mt < 2; mt++) {
                int r = wm * 32 + mt * 16 + (lane & 7) + ((lane >> 3) & 1) * 8;
                int c = kb + (lane >> 4) * 8;
                LDMX4(ahi[mt], smem_u32(&sAhi[r][c]));
                LDMX4(alo[mt], smem_u32(&sAlo[r][c]));
            }
            uint32_t bhi[NTPW][2], blo[NTPW][2];
#pragma unroll
            for (int p = 0; p < NTPW / 2; p++) {
                int n0 = wn * (N / 2) + p * 16;
                int r = n0 + (lane >> 4) * 8 + (lane & 7);
                int c = kb + ((lane >> 3) & 1) * 8;
                uint32_t r4[4];
                LDMX4(r4, smem_u32(&sBhi[r][c]));
                bhi[2 * p][0] = r4[0]; bhi[2 * p][1] = r4[1];
                bhi[2 * p + 1][0] = r4[2]; bhi[2 * p + 1][1] = r4[3];
                LDMX4(r4, smem_u32(&sBlo[r][c]));
                blo[2 * p][0] = r4[0]; blo[2 * p][1] = r4[1];
                blo[2 * p + 1][0] = r4[2]; blo[2 * p + 1][1] = r4[3];
            }
#pragma unroll
            for (int mt = 0; mt < 2; mt++)
#pragma unroll
                for (int nt = 0; nt < NTPW; nt++) {
                    MMA16816(acc[mt][nt], ahi[mt], bhi[nt]);
                    MMA16816(acc[mt][nt], ahi[mt], blo[nt]);
                    MMA16816(acc[mt][nt], alo[mt], bhi[nt]);
                }
        }
        __syncthreads();
    }

    // ---- epilogue: bias + (leaky relu) + (dinv row scale) + store ----
#pragma unroll
    for (int mt = 0; mt < 2; mt++) {
        int row0 = block_row + wm * 32 + mt * 16 + (lane >> 2);
        int row1 = row0 + 8;
        float d0 = 1.f, d1 = 1.f;
        if (SCALE) {
            if (row0 < M) d0 = g_dinv[row0];
            if (row1 < M) d1 = g_dinv[row1];
        }
#pragma unroll
        for (int nt = 0; nt < NTPW; nt++) {
            int col = wn * (N / 2) + nt * 8 + (lane & 3) * 2;
            float bx = bias[col], by = bias[col + 1];
            if (row0 < M) {
                float vx = acc[mt][nt][0] + bx;
                float vy = acc[mt][nt][1] + by;
                if (ACT) {
                    vx = vx > 0.f ? vx : NEG_SLOPE * vx;
                    vy = vy > 0.f ? vy : NEG_SLOPE * vy;
                }
                if (SCALE) { vx *= d0; vy *= d0; }
                *(float2*)&C[(size_t)row0 * N + col] = make_float2(vx, vy);
            }
            if (row1 < M) {
                float vx = acc[mt][nt][2] + bx;
                float vy = acc[mt][nt][3] + by;
                if (ACT) {
                    vx = vx > 0.f ? vx : NEG_SLOPE * vx;
                    vy = vy > 0.f ? vy : NEG_SLOPE * vy;
                }
                if (SCALE) { vx *= d1; vy *= d1; }
                *(float2*)&C[(size_t)row1 * N + col] = make_float2(vx, vy);
            }
        }
    }
}

// ---------------- launch ----------------
extern "C" void kernel_launch(void* const* d_in, const int* in_sizes, int n_in,
                              void* d_out, int out_size) {
    int ix = -1, iei = -1, iencb = -1, iconvb = -1, idecW = -1, idecb = -1;
    for (int i = 0; i < n_in; i++) {
        switch (in_sizes[i]) {
            case 12800000: ix = i;     break;
            case 1600000:  iei = i;    break;
            case 128:      iencb = i;  break;
            case 256:      iconvb = i; break;
            case 8192:     idecW = i;  break;
            case 64:       idecb = i;  break;
            default: break;
        }
    }
    int iencW = -1, iconvW = -1;
    for (int i = 0; i < n_in; i++) {
        if (in_sizes[i] == 32768) {
            if (i == iencb - 1) iencW = i;
            else if (i == iconvb - 1) iconvW = i;
        }
    }
    if (iencW < 0 || iconvW < 0) { iencW = 2; iconvW = 4; }

    const float* x      = (const float*)d_in[ix];
    const void*  ei     = d_in[iei];
    const float* enc_W  = (const float*)d_in[iencW];
    const float* enc_b  = (const float*)d_in[iencb];
    const float* conv_W = (const float*)d_in[iconvW];
    const float* conv_b = (const float*)d_in[iconvb];
    const float* dec_W  = (const float*)d_in[idecW];
    const float* dec_b  = (const float*)d_in[idecb];
    float*       out    = (float*)d_out;

    // ---- preprocessing (4 launches) ----
    k_pre0<<<(N_NODES + 255) / 256, 256>>>(ei);
    k_count_prep<<<COUNT_BLKS + PREPW_BLKS, 256>>>(ei, enc_W, conv_W, dec_W);
    k_scan_dinv<<<1, 1024>>>();
    k_fill<<<(N_EDGES / 2 + 255) / 256, 256>>>(ei);

    const int NTILES = (N_NODES + 127) / 128;   // 391

    // ---- encoder: h0' = dinv * lrelu(x @ enc_W + enc_b) ----
    gemm_mma<IN_DIM, HIDDEN, 0, true, true><<<NTILES, 256>>>(
        x, -1, enc_b, nullptr, 0, N_NODES);

    // ---- GCN layer 0: agg + conv (output scaled for next agg) ----
    int agg_blocks = (N_NODES * 32 + 255) / 256;
    k_agg<<<agg_blocks, 256>>>(0, 1);
    gemm_mma<HIDDEN, HIDDEN, 1, true, true><<<NTILES, 256>>>(
        nullptr, 1, conv_b, nullptr, 0, N_NODES);

    // ---- GCN layer 1: agg + conv (unscaled, feeds decoder) ----
    k_agg<<<agg_blocks, 256>>>(0, 1);
    gemm_mma<HIDDEN, HIDDEN, 2, true, false><<<NTILES, 256>>>(
        nullptr, 1, conv_b + HIDDEN, nullptr, 0, N_NODES);

    // ---- decoder: out = h2 @ dec_W + dec_b ----
    gemm_mma<HIDDEN, OUT_DIM, 3, false, false><<<NTILES, 256>>>(
        nullptr, 0, dec_b, out, -1, N_NODES);
}

// round 13
// speedup vs baseline: 1.0117x; 1.0117x over previous
#include <cuda_runtime.h>
#include <cuda_bf16.h>
#include <cstdint>

#define N_NODES 50000
#define N_EDGES 800000
#define IN_DIM  256
#define HIDDEN  128
#define OUT_DIM 64
#define NEG_SLOPE 0.1f

// ============================ PTX helpers (sm_80+ baseline) ==================
__device__ __forceinline__ uint32_t smem_u32(const void* p) {
    uint32_t a;
    asm("{ .reg .u64 t; cvta.to.shared.u64 t, %1; cvt.u32.u64 %0, t; }"
        : "=r"(a) : "l"(p));
    return a;
}
#define LDMX4(R, addr) \
    asm volatile("ldmatrix.sync.aligned.m8n8.x4.shared.b16 {%0,%1,%2,%3}, [%4];" \
        : "=r"((R)[0]), "=r"((R)[1]), "=r"((R)[2]), "=r"((R)[3]) : "r"(addr))
#define MMA16816(d, a, b) \
    asm volatile("mma.sync.aligned.m16n8k16.row.col.f32.bf16.bf16.f32 " \
        "{%0,%1,%2,%3},{%4,%5,%6,%7},{%8,%9},{%0,%1,%2,%3};" \
        : "+f"((d)[0]), "+f"((d)[1]), "+f"((d)[2]), "+f"((d)[3]) \
        : "r"((a)[0]), "r"((a)[1]), "r"((a)[2]), "r"((a)[3]), \
          "r"((b)[0]), "r"((b)[1]))

__device__ __forceinline__ uint32_t pack_bf2(__nv_bfloat16 a, __nv_bfloat16 b) {
    __nv_bfloat162 p; p.x = a; p.y = b;
    return *(uint32_t*)&p;
}

// ---------------- scratch (static __device__, no allocation) ----------------
__device__ __align__(256) float g_buf0[N_NODES * HIDDEN];
__device__ __align__(256) float g_buf1[N_NODES * HIDDEN];
__device__ float g_dinv[N_NODES];
__device__ int   g_cnt[N_NODES];
__device__ int   g_wp[N_NODES];
__device__ int   g_rowptr[N_NODES + 1];
__device__ int   g_col[N_EDGES];
__device__ int   g_is64;
// pre-transposed + bf16-split weights: Wt[n][k] hi/lo
__device__ __align__(16) __nv_bfloat16 g_wthi_enc[HIDDEN * IN_DIM];
__device__ __align__(16) __nv_bfloat16 g_wtlo_enc[HIDDEN * IN_DIM];
__device__ __align__(16) __nv_bfloat16 g_wthi_conv[2 * HIDDEN * HIDDEN];
__device__ __align__(16) __nv_bfloat16 g_wtlo_conv[2 * HIDDEN * HIDDEN];
__device__ __align__(16) __nv_bfloat16 g_wthi_dec[OUT_DIM * HIDDEN];
__device__ __align__(16) __nv_bfloat16 g_wtlo_dec[OUT_DIM * HIDDEN];

__device__ __forceinline__ const float* resolve_c(const float* p, int sel) {
    if (sel == 0) return g_buf0;
    if (sel == 1) return g_buf1;
    return p;
}
__device__ __forceinline__ float* resolve_m(float* p, int sel) {
    if (sel == 0) return g_buf0;
    if (sel == 1) return g_buf1;
    return p;
}

__device__ __forceinline__ int edge_at(const void* ei, int which, int i) {
    if (g_is64) return (int)((const long long*)ei)[(size_t)which * N_EDGES + i];
    return ((const int*)ei)[which * N_EDGES + i];
}

// ---------------- merged preprocessing ----------------
__global__ void k_pre0(const void* __restrict__ ei) {
    int i = blockIdx.x * blockDim.x + threadIdx.x;
    if (i < N_NODES) { g_cnt[i] = 0; g_wp[i] = 0; }
    if (blockIdx.x == 0) {
        __shared__ int bad64;
        if (threadIdx.x == 0) bad64 = 0;
        __syncthreads();
        const long long* p64 = (const long long*)ei;
        int local = 0;
        for (int t = threadIdx.x; t < 2048; t += blockDim.x) {
            long long v = p64[(long long)t * 390];
            if (v < 0 || v >= N_NODES) local++;
        }
        if (local) atomicAdd(&bad64, local);
        __syncthreads();
        if (threadIdx.x == 0) g_is64 = (bad64 == 0) ? 1 : 0;
    }
}

// degree count (2 edges/thread, first blocks) + weight split (tail blocks)
#define COUNT_BLKS ((N_EDGES / 2 + 255) / 256)      /* 1563 */
#define PREPW_TOT  (HIDDEN * IN_DIM + 2 * HIDDEN * HIDDEN + OUT_DIM * HIDDEN)
#define PREPW_BLKS ((PREPW_TOT + 255) / 256)        /* 288 */
__global__ void k_count_prep(const void* __restrict__ ei,
                             const float* __restrict__ enc_W,
                             const float* __restrict__ conv_W,
                             const float* __restrict__ dec_W) {
    if (blockIdx.x < COUNT_BLKS) {
        int i = (blockIdx.x * 256 + threadIdx.x) * 2;
        if (i < N_EDGES) {
            int d0 = edge_at(ei, 1, i);
            int d1 = (i + 1 < N_EDGES) ? edge_at(ei, 1, i + 1) : -1;
            if ((unsigned)d0 < N_NODES) atomicAdd(&g_cnt[d0], 1);
            if ((unsigned)d1 < N_NODES) atomicAdd(&g_cnt[d1], 1);
        }
    } else {
        int idx = (blockIdx.x - COUNT_BLKS) * 256 + threadIdx.x;
        const int E0 = HIDDEN * IN_DIM;
        const int C0 = E0 + 2 * HIDDEN * HIDDEN;
        if (idx >= PREPW_TOT) return;
        const float* W; __nv_bfloat16 *hi, *lo; int K, N, li;
        if (idx < E0) { W = enc_W; hi = g_wthi_enc; lo = g_wtlo_enc; K = IN_DIM; N = HIDDEN; li = idx; }
        else if (idx < C0) {
            int j = idx - E0; int which = j / (HIDDEN * HIDDEN); li = j % (HIDDEN * HIDDEN);
            W = conv_W + (size_t)which * HIDDEN * HIDDEN;
            hi = g_wthi_conv + (size_t)which * HIDDEN * HIDDEN;
            lo = g_wtlo_conv + (size_t)which * HIDDEN * HIDDEN;
            K = HIDDEN; N = HIDDEN;
        } else { li = idx - C0; W = dec_W; hi = g_wthi_dec; lo = g_wtlo_dec; K = HIDDEN; N = OUT_DIM; }
        int k = li / N, n = li % N;
        float v = W[(size_t)k * N + n];
        __nv_bfloat16 h = __float2bfloat16(v);
        float r = v - __bfloat162float(h);
        hi[(size_t)n * K + k] = h;
        lo[(size_t)n * K + k] = __float2bfloat16(r);
    }
}

// single-block scan + dinv
__global__ void k_scan_dinv() {
    __shared__ int sh[1024];
    const int tid = threadIdx.x;
    const int CH = (N_NODES + 1023) / 1024;
    int start = tid * CH;
    int end   = start + CH; if (end > N_NODES) end = N_NODES;
    int s = 0;
    for (int i = start; i < end; i++) {
        int c = g_cnt[i];
        s += c;
        g_dinv[i] = rsqrtf((float)(c + 1));
    }
    sh[tid] = s;
    __syncthreads();
    for (int d = 1; d < 1024; d <<= 1) {
        int t = (tid >= d) ? sh[tid - d] : 0;
        __syncthreads();
        sh[tid] += t;
        __syncthreads();
    }
    int off = sh[tid] - s;
    for (int i = start; i < end; i++) { g_rowptr[i] = off; off += g_cnt[i]; }
    if (start < N_NODES && end == N_NODES) g_rowptr[N_NODES] = off;
}

// CSR fill, 2 edges per thread
__global__ void k_fill(const void* __restrict__ ei) {
    int i = (blockIdx.x * blockDim.x + threadIdx.x) * 2;
    if (i >= N_EDGES) return;
    int s0 = edge_at(ei, 0, i);
    int d0 = edge_at(ei, 1, i);
    int s1 = -1, d1 = -1;
    if (i + 1 < N_EDGES) { s1 = edge_at(ei, 0, i + 1); d1 = edge_at(ei, 1, i + 1); }
    if ((unsigned)d0 < N_NODES && (unsigned)s0 < N_NODES) {
        int pos = g_rowptr[d0] + atomicAdd(&g_wp[d0], 1);
        g_col[pos] = s0;
    }
    if ((unsigned)d1 < N_NODES && (unsigned)s1 < N_NODES) {
        int pos = g_rowptr[d1] + atomicAdd(&g_wp[d1], 1);
        g_col[pos] = s1;
    }
}

// ---------------- aggregation: one warp per node, SERIAL loop ---------------
// (No manual unroll: keeps MLP_p1 low to avoid cross-CTA L1tex-queue
//  contention spread — the R7/R8 regression mechanism.)
// Input rows pre-scaled: h'[n] = dinv[n]*h[n] (done in GEMM epilogue).
// out[n] = dinv[n] * ( sum_{s in nbr(n)} h'[s] + h'[n] )
__global__ void k_agg(int in_sel, int out_sel) {
    const float* __restrict__ h = resolve_c(nullptr, in_sel);
    float* __restrict__ out = resolve_m(nullptr, out_sel);
    int warp = (blockIdx.x * blockDim.x + threadIdx.x) >> 5;
    int lane = threadIdx.x & 31;
    if (warp >= N_NODES) return;
    const int node = warp;
    const float dn = g_dinv[node];

    float4 acc = *(const float4*)&h[(size_t)node * HIDDEN + lane * 4]; // self h'

    const int beg = g_rowptr[node];
    const int end = g_rowptr[node + 1];
    for (int j = beg; j < end; j++) {
        int s = g_col[j];                 // warp-uniform load
        float4 v = *(const float4*)&h[(size_t)s * HIDDEN + lane * 4];
        acc.x += v.x; acc.y += v.y; acc.z += v.z; acc.w += v.w;
    }
    acc.x *= dn; acc.y *= dn; acc.z *= dn; acc.w *= dn;
    *(float4*)&out[(size_t)node * HIDDEN + lane * 4] = acc;
}

// ============ bf16x3 GEMM via mma.sync.m16n8k16 (sm_80+ baseline) ============
// C[M,N] = act(A[M,KTOT] @ W + b) [optionally * dinv[row]].
// CTA: 256 thr = 8 warps (4m x 2n).  BM=128, BN=N, BK=32.
template <int KTOT, int N, int WSEL, bool ACT, bool SCALE>
__global__ void __launch_bounds__(256, 1)
gemm_mma(const float* __restrict__ A_ext, int a_sel,
         const float* __restrict__ bias,
         float* __restrict__ C_ext, int c_sel, int M) {
    constexpr int NTPW = N / 16;
    const float* __restrict__ A = resolve_c(A_ext, a_sel);
    float* __restrict__ C = resolve_m(C_ext, c_sel);
    const __nv_bfloat16* __restrict__ WtHi;
    const __nv_bfloat16* __restrict__ WtLo;
    if (WSEL == 0)      { WtHi = g_wthi_enc;  WtLo = g_wtlo_enc; }
    else if (WSEL == 1) { WtHi = g_wthi_conv; WtLo = g_wtlo_conv; }
    else if (WSEL == 2) { WtHi = g_wthi_conv + HIDDEN * HIDDEN;
                          WtLo = g_wtlo_conv + HIDDEN * HIDDEN; }
    else                { WtHi = g_wthi_dec;  WtLo = g_wtlo_dec; }

    __shared__ __align__(16) __nv_bfloat16 sAhi[128][40];
    __shared__ __align__(16) __nv_bfloat16 sAlo[128][40];
    __shared__ __align__(16) __nv_bfloat16 sBhi[N][40];
    __shared__ __align__(16) __nv_bfloat16 sBlo[N][40];

    const int tid  = threadIdx.x;
    const int lane = tid & 31;
    const int wid  = tid >> 5;
    const int wm   = wid & 3;
    const int wn   = wid >> 2;
    const int block_row = blockIdx.x * 128;

    float acc[2][NTPW][4];
#pragma unroll
    for (int mt = 0; mt < 2; mt++)
#pragma unroll
        for (int nt = 0; nt < NTPW; nt++)
#pragma unroll
            for (int j = 0; j < 4; j++) acc[mt][nt][j] = 0.0f;

    for (int k0 = 0; k0 < KTOT; k0 += 32) {
        {
            const int row  = tid >> 1;
            const int half = tid & 1;
            const int gr   = block_row + row;
            const float* src = A + (size_t)gr * KTOT + k0 + half * 16;
            const bool ok = gr < M;
#pragma unroll
            for (int j = 0; j < 4; j++) {
                float4 v = ok ? *(const float4*)(src + j * 4)
                              : make_float4(0.f, 0.f, 0.f, 0.f);
                __nv_bfloat16 hx = __float2bfloat16(v.x);
                __nv_bfloat16 hy = __float2bfloat16(v.y);
                __nv_bfloat16 hz = __float2bfloat16(v.z);
                __nv_bfloat16 hw = __float2bfloat16(v.w);
                __nv_bfloat16 lx = __float2bfloat16(v.x - __bfloat162float(hx));
                __nv_bfloat16 ly = __float2bfloat16(v.y - __bfloat162float(hy));
                __nv_bfloat16 lz = __float2bfloat16(v.z - __bfloat162float(hz));
                __nv_bfloat16 lw = __float2bfloat16(v.w - __bfloat162float(hw));
                int col = half * 16 + j * 4;
                *(uint2*)&sAhi[row][col] = make_uint2(pack_bf2(hx, hy), pack_bf2(hz, hw));
                *(uint2*)&sAlo[row][col] = make_uint2(pack_bf2(lx, ly), pack_bf2(lz, lw));
            }
        }
#pragma unroll
        for (int i = tid; i < N * 4; i += 256) {
            int row = i >> 2, q = i & 3;
            *(uint4*)&sBhi[row][q * 8] =
                *(const uint4*)(WtHi + (size_t)row * KTOT + k0 + q * 8);
            *(uint4*)&sBlo[row][q * 8] =
                *(const uint4*)(WtLo + (size_t)row * KTOT + k0 + q * 8);
        }
        __syncthreads();

#pragma unroll
        for (int ks = 0; ks < 2; ks++) {
            const int kb = ks * 16;
            uint32_t ahi[2][4], alo[2][4];
#pragma unroll
            for (int mt = 0; mt < 2; mt++) {
                int r = wm * 32 + mt * 16 + (lane & 7) + ((lane >> 3) & 1) * 8;
                int c = kb + (lane >> 4) * 8;
                LDMX4(ahi[mt], smem_u32(&sAhi[r][c]));
                LDMX4(alo[mt], smem_u32(&sAlo[r][c]));
            }
            uint32_t bhi[NTPW][2], blo[NTPW][2];
#pragma unroll
            for (int p = 0; p < NTPW / 2; p++) {
                int n0 = wn * (N / 2) + p * 16;
                int r = n0 + (lane >> 4) * 8 + (lane & 7);
                int c = kb + ((lane >> 3) & 1) * 8;
                uint32_t r4[4];
                LDMX4(r4, smem_u32(&sBhi[r][c]));
                bhi[2 * p][0] = r4[0]; bhi[2 * p][1] = r4[1];
                bhi[2 * p + 1][0] = r4[2]; bhi[2 * p + 1][1] = r4[3];
                LDMX4(r4, smem_u32(&sBlo[r][c]));
                blo[2 * p][0] = r4[0]; blo[2 * p][1] = r4[1];
                blo[2 * p + 1][0] = r4[2]; blo[2 * p + 1][1] = r4[3];
            }
#pragma unroll
            for (int mt = 0; mt < 2; mt++)
#pragma unroll
                for (int nt = 0; nt < NTPW; nt++) {
                    MMA16816(acc[mt][nt], ahi[mt], bhi[nt]);
                    MMA16816(acc[mt][nt], ahi[mt], blo[nt]);
                    MMA16816(acc[mt][nt], alo[mt], bhi[nt]);
                }
        }
        __syncthreads();
    }

    // ---- epilogue: bias + (leaky relu) + (dinv row scale) + store ----
#pragma unroll
    for (int mt = 0; mt < 2; mt++) {
        int row0 = block_row + wm * 32 + mt * 16 + (lane >> 2);
        int row1 = row0 + 8;
        float d0 = 1.f, d1 = 1.f;
        if (SCALE) {
            if (row0 < M) d0 = g_dinv[row0];
            if (row1 < M) d1 = g_dinv[row1];
        }
#pragma unroll
        for (int nt = 0; nt < NTPW; nt++) {
            int col = wn * (N / 2) + nt * 8 + (lane & 3) * 2;
            float bx = bias[col], by = bias[col + 1];
            if (row0 < M) {
                float vx = acc[mt][nt][0] + bx;
                float vy = acc[mt][nt][1] + by;
                if (ACT) {
                    vx = vx > 0.f ? vx : NEG_SLOPE * vx;
                    vy = vy > 0.f ? vy : NEG_SLOPE * vy;
                }
                if (SCALE) { vx *= d0; vy *= d0; }
                *(float2*)&C[(size_t)row0 * N + col] = make_float2(vx, vy);
            }
            if (row1 < M) {
                float vx = acc[mt][nt][2] + bx;
                float vy = acc[mt][nt][3] + by;
                if (ACT) {
                    vx = vx > 0.f ? vx : NEG_SLOPE * vx;
                    vy = vy > 0.f ? vy : NEG_SLOPE * vy;
                }
                if (SCALE) { vx *= d1; vy *= d1; }
                *(float2*)&C[(size_t)row1 * N + col] = make_float2(vx, vy);
            }
        }
    }
}

// ---------------- launch ----------------
extern "C" void kernel_launch(void* const* d_in, const int* in_sizes, int n_in,
                              void* d_out, int out_size) {
    int ix = -1, iei = -1, iencb = -1, iconvb = -1, idecW = -1, idecb = -1;
    for (int i = 0; i < n_in; i++) {
        switch (in_sizes[i]) {
            case 12800000: ix = i;     break;
            case 1600000:  iei = i;    break;
            case 128:      iencb = i;  break;
            case 256:      iconvb = i; break;
            case 8192:     idecW = i;  break;
            case 64:       idecb = i;  break;
            default: break;
        }
    }
    int iencW = -1, iconvW = -1;
    for (int i = 0; i < n_in; i++) {
        if (in_sizes[i] == 32768) {
            if (i == iencb - 1) iencW = i;
            else if (i == iconvb - 1) iconvW = i;
        }
    }
    if (iencW < 0 || iconvW < 0) { iencW = 2; iconvW = 4; }

    const float* x      = (const float*)d_in[ix];
    const void*  ei     = d_in[iei];
    const float* enc_W  = (const float*)d_in[iencW];
    const float* enc_b  = (const float*)d_in[iencb];
    const float* conv_W = (const float*)d_in[iconvW];
    const float* conv_b = (const float*)d_in[iconvb];
    const float* dec_W  = (const float*)d_in[idecW];
    const float* dec_b  = (const float*)d_in[idecb];
    float*       out    = (float*)d_out;

    // ---- preprocessing (4 launches) ----
    k_pre0<<<(N_NODES + 255) / 256, 256>>>(ei);
    k_count_prep<<<COUNT_BLKS + PREPW_BLKS, 256>>>(ei, enc_W, conv_W, dec_W);
    k_scan_dinv<<<1, 1024>>>();
    k_fill<<<(N_EDGES / 2 + 255) / 256, 256>>>(ei);

    const int NTILES = (N_NODES + 127) / 128;   // 391

    // ---- encoder: h0' = dinv * lrelu(x @ enc_W + enc_b) ----
    gemm_mma<IN_DIM, HIDDEN, 0, true, true><<<NTILES, 256>>>(
        x, -1, enc_b, nullptr, 0, N_NODES);

    // ---- GCN layer 0: agg + conv (output scaled for next agg) ----
    int agg_blocks = (N_NODES * 32 + 255) / 256;
    k_agg<<<agg_blocks, 256>>>(0, 1);
    gemm_mma<HIDDEN, HIDDEN, 1, true, true><<<NTILES, 256>>>(
        nullptr, 1, conv_b, nullptr, 0, N_NODES);

    // ---- GCN layer 1: agg + conv (unscaled, feeds decoder) ----
    k_agg<<<agg_blocks, 256>>>(0, 1);
    gemm_mma<HIDDEN, HIDDEN, 2, true, false><<<NTILES, 256>>>(
        nullptr, 1, conv_b + HIDDEN, nullptr, 0, N_NODES);

    // ---- decoder: out = h2 @ dec_W + dec_b ----
    gemm_mma<HIDDEN, OUT_DIM, 3, false, false><<<NTILES, 256>>>(
        nullptr, 0, dec_b, out, -1, N_NODES);
}

// round 16
// speedup vs baseline: 1.0476x; 1.0355x over previous
#include <cuda_runtime.h>
#include <cuda_bf16.h>
#include <cuda_fp16.h>
#include <cstdint>

#define N_NODES 50000
#define N_EDGES 800000
#define IN_DIM  256
#define HIDDEN  128
#define OUT_DIM 64
#define NEG_SLOPE 0.1f

// ============================ PTX helpers (sm_80+ baseline) ==================
__device__ __forceinline__ uint32_t smem_u32(const void* p) {
    uint32_t a;
    asm("{ .reg .u64 t; cvta.to.shared.u64 t, %1; cvt.u32.u64 %0, t; }"
        : "=r"(a) : "l"(p));
    return a;
}
#define LDMX4(R, addr) \
    asm volatile("ldmatrix.sync.aligned.m8n8.x4.shared.b16 {%0,%1,%2,%3}, [%4];" \
        : "=r"((R)[0]), "=r"((R)[1]), "=r"((R)[2]), "=r"((R)[3]) : "r"(addr))
#define MMA16816(d, a, b) \
    asm volatile("mma.sync.aligned.m16n8k16.row.col.f32.bf16.bf16.f32 " \
        "{%0,%1,%2,%3},{%4,%5,%6,%7},{%8,%9},{%0,%1,%2,%3};" \
        : "+f"((d)[0]), "+f"((d)[1]), "+f"((d)[2]), "+f"((d)[3]) \
        : "r"((a)[0]), "r"((a)[1]), "r"((a)[2]), "r"((a)[3]), \
          "r"((b)[0]), "r"((b)[1]))

__device__ __forceinline__ uint32_t pack_bf2(__nv_bfloat16 a, __nv_bfloat16 b) {
    __nv_bfloat162 p; p.x = a; p.y = b;
    return *(uint32_t*)&p;
}

// ---------------- scratch (static __device__, no allocation) ----------------
__device__ __align__(256) float  g_buf0[N_NODES * HIDDEN];   // conv1 out (fp32)
__device__ __align__(256) float  g_buf1[N_NODES * HIDDEN];   // agg out (fp32)
__device__ __align__(256) __half g_h16[N_NODES * HIDDEN];    // gather source (fp16)
__device__ float g_dinv[N_NODES];
__device__ int   g_cnt[N_NODES];
__device__ int   g_wp[N_NODES];
__device__ int   g_rowptr[N_NODES + 1];
__device__ int   g_col[N_EDGES];
__device__ int   g_is64;
// pre-transposed + bf16-split weights: Wt[n][k] hi/lo
__device__ __align__(16) __nv_bfloat16 g_wthi_enc[HIDDEN * IN_DIM];
__device__ __align__(16) __nv_bfloat16 g_wtlo_enc[HIDDEN * IN_DIM];
__device__ __align__(16) __nv_bfloat16 g_wthi_conv[2 * HIDDEN * HIDDEN];
__device__ __align__(16) __nv_bfloat16 g_wtlo_conv[2 * HIDDEN * HIDDEN];
__device__ __align__(16) __nv_bfloat16 g_wthi_dec[OUT_DIM * HIDDEN];
__device__ __align__(16) __nv_bfloat16 g_wtlo_dec[OUT_DIM * HIDDEN];

__device__ __forceinline__ const float* resolve_c(const float* p, int sel) {
    if (sel == 0) return g_buf0;
    if (sel == 1) return g_buf1;
    return p;
}
__device__ __forceinline__ float* resolve_m(float* p, int sel) {
    if (sel == 0) return g_buf0;
    if (sel == 1) return g_buf1;
    return p;
}

__device__ __forceinline__ int edge_at(const void* ei, int which, int i) {
    if (g_is64) return (int)((const long long*)ei)[(size_t)which * N_EDGES + i];
    return ((const int*)ei)[which * N_EDGES + i];
}

// ---------------- merged preprocessing ----------------
__global__ void k_pre0(const void* __restrict__ ei) {
    int i = blockIdx.x * blockDim.x + threadIdx.x;
    if (i < N_NODES) { g_cnt[i] = 0; g_wp[i] = 0; }
    if (blockIdx.x == 0) {
        __shared__ int bad64;
        if (threadIdx.x == 0) bad64 = 0;
        __syncthreads();
        const long long* p64 = (const long long*)ei;
        int local = 0;
        for (int t = threadIdx.x; t < 2048; t += blockDim.x) {
            long long v = p64[(long long)t * 390];
            if (v < 0 || v >= N_NODES) local++;
        }
        if (local) atomicAdd(&bad64, local);
        __syncthreads();
        if (threadIdx.x == 0) g_is64 = (bad64 == 0) ? 1 : 0;
    }
}

// degree count (2 edges/thread, first blocks) + weight split (tail blocks)
#define COUNT_BLKS ((N_EDGES / 2 + 255) / 256)      /* 1563 */
#define PREPW_TOT  (HIDDEN * IN_DIM + 2 * HIDDEN * HIDDEN + OUT_DIM * HIDDEN)
#define PREPW_BLKS ((PREPW_TOT + 255) / 256)        /* 288 */
__global__ void k_count_prep(const void* __restrict__ ei,
                             const float* __restrict__ enc_W,
                             const float* __restrict__ conv_W,
                             const float* __restrict__ dec_W) {
    if (blockIdx.x < COUNT_BLKS) {
        int i = (blockIdx.x * 256 + threadIdx.x) * 2;
        if (i < N_EDGES) {
            int d0 = edge_at(ei, 1, i);
            int d1 = (i + 1 < N_EDGES) ? edge_at(ei, 1, i + 1) : -1;
            if ((unsigned)d0 < N_NODES) atomicAdd(&g_cnt[d0], 1);
            if ((unsigned)d1 < N_NODES) atomicAdd(&g_cnt[d1], 1);
        }
    } else {
        int idx = (blockIdx.x - COUNT_BLKS) * 256 + threadIdx.x;
        const int E0 = HIDDEN * IN_DIM;
        const int C0 = E0 + 2 * HIDDEN * HIDDEN;
        if (idx >= PREPW_TOT) return;
        const float* W; __nv_bfloat16 *hi, *lo; int K, N, li;
        if (idx < E0) { W = enc_W; hi = g_wthi_enc; lo = g_wtlo_enc; K = IN_DIM; N = HIDDEN; li = idx; }
        else if (idx < C0) {
            int j = idx - E0; int which = j / (HIDDEN * HIDDEN); li = j % (HIDDEN * HIDDEN);
            W = conv_W + (size_t)which * HIDDEN * HIDDEN;
            hi = g_wthi_conv + (size_t)which * HIDDEN * HIDDEN;
            lo = g_wtlo_conv + (size_t)which * HIDDEN * HIDDEN;
            K = HIDDEN; N = HIDDEN;
        } else { li = idx - C0; W = dec_W; hi = g_wthi_dec; lo = g_wtlo_dec; K = HIDDEN; N = OUT_DIM; }
        int k = li / N, n = li % N;
        float v = W[(size_t)k * N + n];
        __nv_bfloat16 h = __float2bfloat16(v);
        float r = v - __bfloat162float(h);
        hi[(size_t)n * K + k] = h;
        lo[(size_t)n * K + k] = __float2bfloat16(r);
    }
}

// single-block scan + dinv
__global__ void k_scan_dinv() {
    __shared__ int sh[1024];
    const int tid = threadIdx.x;
    const int CH = (N_NODES + 1023) / 1024;
    int start = tid * CH;
    int end   = start + CH; if (end > N_NODES) end = N_NODES;
    int s = 0;
    for (int i = start; i < end; i++) {
        int c = g_cnt[i];
        s += c;
        g_dinv[i] = rsqrtf((float)(c + 1));
    }
    sh[tid] = s;
    __syncthreads();
    for (int d = 1; d < 1024; d <<= 1) {
        int t = (tid >= d) ? sh[tid - d] : 0;
        __syncthreads();
        sh[tid] += t;
        __syncthreads();
    }
    int off = sh[tid] - s;
    for (int i = start; i < end; i++) { g_rowptr[i] = off; off += g_cnt[i]; }
    if (start < N_NODES && end == N_NODES) g_rowptr[N_NODES] = off;
}

// CSR fill, 2 edges per thread
__global__ void k_fill(const void* __restrict__ ei) {
    int i = (blockIdx.x * blockDim.x + threadIdx.x) * 2;
    if (i >= N_EDGES) return;
    int s0 = edge_at(ei, 0, i);
    int d0 = edge_at(ei, 1, i);
    int s1 = -1, d1 = -1;
    if (i + 1 < N_EDGES) { s1 = edge_at(ei, 0, i + 1); d1 = edge_at(ei, 1, i + 1); }
    if ((unsigned)d0 < N_NODES && (unsigned)s0 < N_NODES) {
        int pos = g_rowptr[d0] + atomicAdd(&g_wp[d0], 1);
        g_col[pos] = s0;
    }
    if ((unsigned)d1 < N_NODES && (unsigned)s1 < N_NODES) {
        int pos = g_rowptr[d1] + atomicAdd(&g_wp[d1], 1);
        g_col[pos] = s1;
    }
}

// ---------------- aggregation: one warp per node, fp16 gather ---------------
// Gathers pre-scaled fp16 rows h'[s] from g_h16 (256B/row: half the L2
// traffic of fp32), accumulates fp32, writes fp32 for the next GEMM.
// out[n] = dinv[n] * ( sum_{s in nbr(n)} h'[s] + h'[n] )
__global__ void k_agg(int out_sel) {
    const __half* __restrict__ h = g_h16;
    float* __restrict__ out = resolve_m(nullptr, out_sel);
    int warp = (blockIdx.x * blockDim.x + threadIdx.x) >> 5;
    int lane = threadIdx.x & 31;
    if (warp >= N_NODES) return;
    const int node = warp;
    const float dn = g_dinv[node];

    float ax, ay, az, aw;
    {   // self term
        uint2 u = *(const uint2*)&h[(size_t)node * HIDDEN + lane * 4];
        float2 f0 = __half22float2(*(__half2*)&u.x);
        float2 f1 = __half22float2(*(__half2*)&u.y);
        ax = f0.x; ay = f0.y; az = f1.x; aw = f1.y;
    }

    const int beg = g_rowptr[node];
    const int end = g_rowptr[node + 1];
    for (int j = beg; j < end; j++) {
        int s = g_col[j];                 // warp-uniform load
        uint2 u = *(const uint2*)&h[(size_t)s * HIDDEN + lane * 4];
        float2 f0 = __half22float2(*(__half2*)&u.x);
        float2 f1 = __half22float2(*(__half2*)&u.y);
        ax += f0.x; ay += f0.y; az += f1.x; aw += f1.y;
    }
    float4 r = make_float4(dn * ax, dn * ay, dn * az, dn * aw);
    *(float4*)&out[(size_t)node * HIDDEN + lane * 4] = r;
}

// ============ bf16x3 GEMM via mma.sync.m16n8k16 (sm_80+ baseline) ============
// C = act(A @ W + b) [* dinv[row] if SCALE].  If OUT16: write fp16 to g_h16
// (for the aggregation gather); else write fp32 to C.
template <int KTOT, int N, int WSEL, bool ACT, bool SCALE, bool OUT16>
__global__ void __launch_bounds__(256, 1)
gemm_mma(const float* __restrict__ A_ext, int a_sel,
         const float* __restrict__ bias,
         float* __restrict__ C_ext, int c_sel, int M) {
    constexpr int NTPW = N / 16;
    const float* __restrict__ A = resolve_c(A_ext, a_sel);
    float* __restrict__ C = resolve_m(C_ext, c_sel);
    const __nv_bfloat16* __restrict__ WtHi;
    const __nv_bfloat16* __restrict__ WtLo;
    if (WSEL == 0)      { WtHi = g_wthi_enc;  WtLo = g_wtlo_enc; }
    else if (WSEL == 1) { WtHi = g_wthi_conv; WtLo = g_wtlo_conv; }
    else if (WSEL == 2) { WtHi = g_wthi_conv + HIDDEN * HIDDEN;
                          WtLo = g_wtlo_conv + HIDDEN * HIDDEN; }
    else                { WtHi = g_wthi_dec;  WtLo = g_wtlo_dec; }

    __shared__ __align__(16) __nv_bfloat16 sAhi[128][40];
    __shared__ __align__(16) __nv_bfloat16 sAlo[128][40];
    __shared__ __align__(16) __nv_bfloat16 sBhi[N][40];
    __shared__ __align__(16) __nv_bfloat16 sBlo[N][40];

    const int tid  = threadIdx.x;
    const int lane = tid & 31;
    const int wid  = tid >> 5;
    const int wm   = wid & 3;
    const int wn   = wid >> 2;
    const int block_row = blockIdx.x * 128;

    float acc[2][NTPW][4];
#pragma unroll
    for (int mt = 0; mt < 2; mt++)
#pragma unroll
        for (int nt = 0; nt < NTPW; nt++)
#pragma unroll
            for (int j = 0; j < 4; j++) acc[mt][nt][j] = 0.0f;

    for (int k0 = 0; k0 < KTOT; k0 += 32) {
        {
            const int row  = tid >> 1;
            const int half = tid & 1;
            const int gr   = block_row + row;
            const float* src = A + (size_t)gr * KTOT + k0 + half * 16;
            const bool ok = gr < M;
#pragma unroll
            for (int j = 0; j < 4; j++) {
                float4 v = ok ? *(const float4*)(src + j * 4)
                              : make_float4(0.f, 0.f, 0.f, 0.f);
                __nv_bfloat16 hx = __float2bfloat16(v.x);
                __nv_bfloat16 hy = __float2bfloat16(v.y);
                __nv_bfloat16 hz = __float2bfloat16(v.z);
                __nv_bfloat16 hw = __float2bfloat16(v.w);
                __nv_bfloat16 lx = __float2bfloat16(v.x - __bfloat162float(hx));
                __nv_bfloat16 ly = __float2bfloat16(v.y - __bfloat162float(hy));
                __nv_bfloat16 lz = __float2bfloat16(v.z - __bfloat162float(hz));
                __nv_bfloat16 lw = __float2bfloat16(v.w - __bfloat162float(hw));
                int col = half * 16 + j * 4;
                *(uint2*)&sAhi[row][col] = make_uint2(pack_bf2(hx, hy), pack_bf2(hz, hw));
                *(uint2*)&sAlo[row][col] = make_uint2(pack_bf2(lx, ly), pack_bf2(lz, lw));
            }
        }
#pragma unroll
        for (int i = tid; i < N * 4; i += 256) {
            int row = i >> 2, q = i & 3;
            *(uint4*)&sBhi[row][q * 8] =
                *(const uint4*)(WtHi + (size_t)row * KTOT + k0 + q * 8);
            *(uint4*)&sBlo[row][q * 8] =
                *(const uint4*)(WtLo + (size_t)row * KTOT + k0 + q * 8);
        }
        __syncthreads();

#pragma unroll
        for (int ks = 0; ks < 2; ks++) {
            const int kb = ks * 16;
            uint32_t ahi[2][4], alo[2][4];
#pragma unroll
            for (int mt = 0; mt < 2; mt++) {
                int r = wm * 32 + mt * 16 + (lane & 7) + ((lane >> 3) & 1) * 8;
                int c = kb + (lane >> 4) * 8;
                LDMX4(ahi[mt], smem_u32(&sAhi[r][c]));
                LDMX4(alo[mt], smem_u32(&sAlo[r][c]));
            }
            uint32_t bhi[NTPW][2], blo[NTPW][2];
#pragma unroll
            for (int p = 0; p < NTPW / 2; p++) {
                int n0 = wn * (N / 2) + p * 16;
                int r = n0 + (lane >> 4) * 8 + (lane & 7);
                int c = kb + ((lane >> 3) & 1) * 8;
                uint32_t r4[4];
                LDMX4(r4, smem_u32(&sBhi[r][c]));
                bhi[2 * p][0] = r4[0]; bhi[2 * p][1] = r4[1];
                bhi[2 * p + 1][0] = r4[2]; bhi[2 * p + 1][1] = r4[3];
                LDMX4(r4, smem_u32(&sBlo[r][c]));
                blo[2 * p][0] = r4[0]; blo[2 * p][1] = r4[1];
                blo[2 * p + 1][0] = r4[2]; blo[2 * p + 1][1] = r4[3];
            }
#pragma unroll
            for (int mt = 0; mt < 2; mt++)
#pragma unroll
                for (int nt = 0; nt < NTPW; nt++) {
                    MMA16816(acc[mt][nt], ahi[mt], bhi[nt]);
                    MMA16816(acc[mt][nt], ahi[mt], blo[nt]);
                    MMA16816(acc[mt][nt], alo[mt], bhi[nt]);
                }
        }
        __syncthreads();
    }

    // ---- epilogue: bias + (leaky relu) + (dinv scale) + store (fp32|fp16) ---
#pragma unroll
    for (int mt = 0; mt < 2; mt++) {
        int row0 = block_row + wm * 32 + mt * 16 + (lane >> 2);
        int row1 = row0 + 8;
        float d0 = 1.f, d1 = 1.f;
        if (SCALE) {
            if (row0 < M) d0 = g_dinv[row0];
            if (row1 < M) d1 = g_dinv[row1];
        }
#pragma unroll
        for (int nt = 0; nt < NTPW; nt++) {
            int col = wn * (N / 2) + nt * 8 + (lane & 3) * 2;
            float bx = bias[col], by = bias[col + 1];
            if (row0 < M) {
                float vx = acc[mt][nt][0] + bx;
                float vy = acc[mt][nt][1] + by;
                if (ACT) {
                    vx = vx > 0.f ? vx : NEG_SLOPE * vx;
                    vy = vy > 0.f ? vy : NEG_SLOPE * vy;
                }
                if (SCALE) { vx *= d0; vy *= d0; }
                if (OUT16)
                    *(__half2*)&g_h16[(size_t)row0 * N + col] = __floats2half2_rn(vx, vy);
                else
                    *(float2*)&C[(size_t)row0 * N + col] = make_float2(vx, vy);
            }
            if (row1 < M) {
                float vx = acc[mt][nt][2] + bx;
                float vy = acc[mt][nt][3] + by;
                if (ACT) {
                    vx = vx > 0.f ? vx : NEG_SLOPE * vx;
                    vy = vy > 0.f ? vy : NEG_SLOPE * vy;
                }
                if (SCALE) { vx *= d1; vy *= d1; }
                if (OUT16)
                    *(__half2*)&g_h16[(size_t)row1 * N + col] = __floats2half2_rn(vx, vy);
                else
                    *(float2*)&C[(size_t)row1 * N + col] = make_float2(vx, vy);
            }
        }
    }
}

// ---------------- launch ----------------
extern "C" void kernel_launch(void* const* d_in, const int* in_sizes, int n_in,
                              void* d_out, int out_size) {
    int ix = -1, iei = -1, iencb = -1, iconvb = -1, idecW = -1, idecb = -1;
    for (int i = 0; i < n_in; i++) {
        switch (in_sizes[i]) {
            case 12800000: ix = i;     break;
            case 1600000:  iei = i;    break;
            case 128:      iencb = i;  break;
            case 256:      iconvb = i; break;
            case 8192:     idecW = i;  break;
            case 64:       idecb = i;  break;
            default: break;
        }
    }
    int iencW = -1, iconvW = -1;
    for (int i = 0; i < n_in; i++) {
        if (in_sizes[i] == 32768) {
            if (i == iencb - 1) iencW = i;
            else if (i == iconvb - 1) iconvW = i;
        }
    }
    if (iencW < 0 || iconvW < 0) { iencW = 2; iconvW = 4; }

    const float* x      = (const float*)d_in[ix];
    const void*  ei     = d_in[iei];
    const float* enc_W  = (const float*)d_in[iencW];
    const float* enc_b  = (const float*)d_in[iencb];
    const float* conv_W = (const float*)d_in[iconvW];
    const float* conv_b = (const float*)d_in[iconvb];
    const float* dec_W  = (const float*)d_in[idecW];
    const float* dec_b  = (const float*)d_in[idecb];
    float*       out    = (float*)d_out;

    // ---- preprocessing (4 launches) ----
    k_pre0<<<(N_NODES + 255) / 256, 256>>>(ei);
    k_count_prep<<<COUNT_BLKS + PREPW_BLKS, 256>>>(ei, enc_W, conv_W, dec_W);
    k_scan_dinv<<<1, 1024>>>();
    k_fill<<<(N_EDGES / 2 + 255) / 256, 256>>>(ei);

    const int NTILES = (N_NODES + 127) / 128;   // 391
    const int agg_blocks = (N_NODES * 32 + 255) / 256;

    // ---- encoder: g_h16 = fp16( dinv * lrelu(x @ enc_W + enc_b) ) ----
    gemm_mma<IN_DIM, HIDDEN, 0, true, true, true><<<NTILES, 256>>>(
        x, -1, enc_b, nullptr, -1, N_NODES);

    // ---- GCN layer 0: fp16 agg -> fp32 buf1; conv -> g_h16 ----
    k_agg<<<agg_blocks, 256>>>(1);
    gemm_mma<HIDDEN, HIDDEN, 1, true, true, true><<<NTILES, 256>>>(
        nullptr, 1, conv_b, nullptr, -1, N_NODES);

    // ---- GCN layer 1: fp16 agg -> fp32 buf1; conv -> fp32 buf0 ----
    k_agg<<<agg_blocks, 256>>>(1);
    gemm_mma<HIDDEN, HIDDEN, 2, true, false, false><<<NTILES, 256>>>(
        nullptr, 1, conv_b + HIDDEN, nullptr, 0, N_NODES);

    // ---- decoder: out = buf0 @ dec_W + dec_b ----
    gemm_mma<HIDDEN, OUT_DIM, 3, false, false, false><<<NTILES, 256>>>(
        nullptr, 0, dec_b, out, -1, N_NODES);
}